// round 16
// baseline (speedup 1.0000x reference)
#include <cuda_runtime.h>
#include <cuda_fp16.h>

// AdderNet SAD-conv. fp16x2 inner loop (pack along M, broadcast x).
// R16 = R11 (159.7us pass) + ONE diff: fp16 partial promote every 2 chunks
//       (16 channels; was 8) -> 4 promote events instead of 8, ~1.4% less
//       fma-pipe work. Calibrated rel_err prediction ~7.5e-4 (gate 1e-3,
//       fixed-seed deterministic input).
// Everything else byte-identical to R11 (preamble has passed 5x in this form).
//
// x (32,64,32,32) f32, W (128,64,3,3) f32, bits int32 -> out (32,128,32,32) f32

#define C_IN   64
#define H_IN   32
#define W_IN   32
#define M_OUT  128
#define KK     (C_IN * 9)   // 576
#define BATCH  32
#define CB     8            // channels per chunk (8 chunks)
#define MB     64           // filters per block (gridDim.z = 2)
#define XROW   40           // padded x row width (halves); 80B, 16B-aligned

__device__ int   g_absmax_bits;
__device__ float g_bias[M_OUT];
__device__ __align__(16) __half g_Wh[KK * M_OUT];                  // k-major, m contig
__device__ __align__(16) __half g_xh[BATCH * C_IN * 34 * XROW];    // padded fp16 x

// ---------------------------------------------------------------------------
__global__ void k_init() { g_absmax_bits = 0; }

__global__ void k_scale(const float* __restrict__ W) {
    __shared__ float red[8];
    float m = 0.f;
    for (int i = blockIdx.x * 256 + threadIdx.x; i < M_OUT * KK; i += gridDim.x * 256)
        m = fmaxf(m, fabsf(W[i]));
    #pragma unroll
    for (int o = 16; o; o >>= 1) m = fmaxf(m, __shfl_xor_sync(0xffffffffu, m, o));
    if ((threadIdx.x & 31) == 0) red[threadIdx.x >> 5] = m;
    __syncthreads();
    if (threadIdx.x == 0) {
        float v = red[0];
        #pragma unroll
        for (int i = 1; i < 8; i++) v = fmaxf(v, red[i]);
        atomicMax(&g_absmax_bits, __float_as_int(v));   // nonneg: int-max == float-max
    }
}

// ---------------------------------------------------------------------------
__global__ void k_quant(const float* __restrict__ W, const int* __restrict__ bits_p) {
    const int m = blockIdx.x;
    const int bits = *bits_p;
    const float qmx = (float)((1 << (bits - 1)) - 1);
    const float qmn = -(float)(1 << (bits - 1));
    const float alpha = __int_as_float(g_absmax_bits);
    const float s = fmaxf(alpha / qmx, 1e-6f);

    float sum = 0.f;
    for (int k = threadIdx.x; k < KK; k += 256) {
        float w  = W[m * KK + k];
        float q  = rintf(w / s);                      // round half-to-even == jnp.round
        q        = fminf(fmaxf(q, qmn), qmx);
        float wc = q * s;
        g_Wh[k * M_OUT + m] = __float2half(wc);
        sum += fabsf(w - wc);
    }
    __shared__ float red[8];
    #pragma unroll
    for (int o = 16; o; o >>= 1) sum += __shfl_xor_sync(0xffffffffu, sum, o);
    if ((threadIdx.x & 31) == 0) red[threadIdx.x >> 5] = sum;
    __syncthreads();
    if (threadIdx.x == 0) {
        float t = 0.f;
        #pragma unroll
        for (int i = 0; i < 8; i++) t += red[i];
        g_bias[m] = -t;
    }
}

// ---------------------------------------------------------------------------
// Pre-pad x -> fp16: g_xh[b][c][0..33][0..39]; interior rows/cols 1..32 hold
// x, the rest zero. 2048 blocks (b*64+c), 128 threads.
// ---------------------------------------------------------------------------
__global__ void k_pad(const float* __restrict__ x) {
    const int bc = blockIdx.x;
    const float* src = x + (size_t)bc * H_IN * W_IN;
    __half* dst = g_xh + (size_t)bc * 34 * XROW;
    for (int idx = threadIdx.x; idx < 34 * XROW; idx += 128) {
        int row = idx / XROW;
        int col = idx - row * XROW;
        float v = 0.f;
        if ((unsigned)(row - 1) < H_IN && (unsigned)(col - 1) < W_IN)
            v = src[(row - 1) * W_IN + (col - 1)];
        dst[idx] = __float2half(v);
    }
}

// ---------------------------------------------------------------------------
// K2: main SAD. grid (H_IN, BATCH, 2) = 2048 blocks, 128 threads.
// thread (tm = tid>>3, tp = tid&7): m = mz + tm*4 (2 half2), w in [tp*4, +4).
// Register-staged pipeline: LDG chunk s+1 into regs while computing chunk s.
// ---------------------------------------------------------------------------
__global__ void __launch_bounds__(128)
k_main(float* __restrict__ out) {
    __shared__ __align__(16) __half sW[CB * 9][MB];   // 72 x 64 halves = 9216 B
    __shared__ __align__(16) __half sX[CB][3][XROW];  // 1920 B

    const int h0  = blockIdx.x;
    const int b   = blockIdx.y;
    const int mz  = blockIdx.z * MB;
    const int tid = threadIdx.x;
    const int tm  = tid >> 3;    // 0..15
    const int tp  = tid & 7;     // 0..7
    const int m0  = tm * 4;      // within MB slice
    const int w0  = tp * 4;

    // per-thread fill assignment (constant across chunks)
    const int  wrow[5] = { tid >> 3, (tid + 128) >> 3, (tid + 256) >> 3,
                           (tid + 384) >> 3, (tid + 512) >> 3 };
    const int  wcol    = tid & 7;
    const bool w5      = (tid < 64);
    const bool  xact = (tid < CB * 3 * 5);
    const int   xci  = tid / 15;
    const int   xr_  = tid - xci * 15;
    const int   xdh  = xr_ / 5;
    const int   xq   = xr_ - xdh * 5;

    const __half* wbase0 = g_Wh + mz;
    const __half* xbase0 = g_xh + (((size_t)b * C_IN) * 34 + h0) * XROW;

    uint4 wreg[5];
    uint4 xreg;

    // --- prefetch chunk 0 ---
    {
        #pragma unroll
        for (int i = 0; i < 4; i++)
            wreg[i] = *(const uint4*)(wbase0 + (size_t)wrow[i] * M_OUT + wcol * 8);
        wreg[4] = w5 ? *(const uint4*)(wbase0 + (size_t)wrow[4] * M_OUT + wcol * 8) : wreg[0];
        if (xact)
            xreg = *(const uint4*)(xbase0 + ((size_t)xci * 34 + xdh) * XROW + xq * 8);
    }

    float accf[4][4];
    #pragma unroll
    for (int i = 0; i < 4; i++)
        #pragma unroll
        for (int j = 0; j < 4; j++) accf[i][j] = 0.f;

    half2 acc2[2][4];
    const half2 h2z = __float2half2_rn(0.f);
    #pragma unroll
    for (int p = 0; p < 2; p++)
        #pragma unroll
        for (int j = 0; j < 4; j++) acc2[p][j] = h2z;

    const int NCHUNK = C_IN / CB;   // 8
    for (int s = 0; s < NCHUNK; s++) {
        if (s) __syncthreads();      // all warps done reading smem for chunk s-1
        // publish chunk s from registers
        #pragma unroll
        for (int i = 0; i < 4; i++)
            *(uint4*)&sW[wrow[i]][wcol * 8] = wreg[i];
        if (w5) *(uint4*)&sW[wrow[4]][wcol * 8] = wreg[4];
        if (xact) *(uint4*)&sX[xci][xdh][xq * 8] = xreg;
        __syncthreads();

        // prefetch chunk s+1 (latency hidden under compute below)
        if (s + 1 < NCHUNK) {
            const __half* gw = wbase0 + (size_t)(s + 1) * CB * 9 * M_OUT;
            const __half* gx = xbase0 + (size_t)(s + 1) * CB * 34 * XROW;
            #pragma unroll
            for (int i = 0; i < 4; i++)
                wreg[i] = *(const uint4*)(gw + (size_t)wrow[i] * M_OUT + wcol * 8);
            if (w5) wreg[4] = *(const uint4*)(gw + (size_t)wrow[4] * M_OUT + wcol * 8);
            if (xact) xreg = *(const uint4*)(gx + ((size_t)xci * 34 + xdh) * XROW + xq * 8);
        }

        // compute chunk s
        #pragma unroll
        for (int ci = 0; ci < CB; ci++) {
            half2 xv[3][3];
            #pragma unroll
            for (int dh = 0; dh < 3; dh++) {
                xv[dh][0] = *(const half2*)&sX[ci][dh][w0];
                xv[dh][1] = *(const half2*)&sX[ci][dh][w0 + 2];
                xv[dh][2] = *(const half2*)&sX[ci][dh][w0 + 4];
            }

            #pragma unroll
            for (int t = 0; t < 9; t++) {
                const int dh = t / 3;
                const int dw = t - 3 * dh;
                uint2 wraw = *(const uint2*)&sW[ci * 9 + t][m0];  // 4 halves
                half2 wp[2];
                wp[0] = *(half2*)&wraw.x;
                wp[1] = *(half2*)&wraw.y;
                #pragma unroll
                for (int j = 0; j < 4; j++) {
                    const int sidx = dw + j;            // 0..5, compile-time
                    half2 r = xv[dh][sidx >> 1];
                    half2 xbc = (sidx & 1) ? __high2half2(r) : __low2half2(r);
                    #pragma unroll
                    for (int p = 0; p < 2; p++)
                        acc2[p][j] = __hadd2(acc2[p][j],
                                             __habs2(__hsub2(wp[p], xbc)));
                }
            }

            // promote fp16 partials every 2 chunks (16 channels)
            if (ci == CB - 1 && (s & 1)) {
                #pragma unroll
                for (int p = 0; p < 2; p++)
                    #pragma unroll
                    for (int j = 0; j < 4; j++) {
                        float2 f = __half22float2(acc2[p][j]);
                        accf[2 * p][j]     += f.x;
                        accf[2 * p + 1][j] += f.y;
                        acc2[p][j] = h2z;
                    }
            }
        }
    }

    // epilogue: out[b][m][h0][w] = bias[m] - sum
    #pragma unroll
    for (int i = 0; i < 4; i++) {
        const int m = mz + m0 + i;
        float bv = g_bias[m];
        float4 o;
        o.x = bv - accf[i][0];
        o.y = bv - accf[i][1];
        o.z = bv - accf[i][2];
        o.w = bv - accf[i][3];
        *(float4*)(out + (((size_t)b * M_OUT + m) * H_IN + h0) * W_IN + w0) = o;
    }
}

// ---------------------------------------------------------------------------
extern "C" void kernel_launch(void* const* d_in, const int* in_sizes, int n_in,
                              void* d_out, int out_size) {
    const float* x    = (const float*)d_in[0];
    const float* W    = (const float*)d_in[1];
    const int*   bits = (const int*)d_in[2];
    float*       out  = (float*)d_out;

    k_init<<<1, 1>>>();
    k_scale<<<32, 256>>>(W);
    k_pad<<<BATCH * C_IN, 128>>>(x);
    k_quant<<<M_OUT, 256>>>(W, bits);
    dim3 grid(H_IN, BATCH, 2);
    k_main<<<grid, 128>>>(out);
}

// round 17
// speedup vs baseline: 1.0256x; 1.0256x over previous
#include <cuda_runtime.h>
#include <cuda_fp16.h>

// AdderNet SAD-conv. fp16x2 inner loop (pack along M, broadcast x).
// R17 = R11 byte-for-byte (best: 159.7us, rel_err 3.82e-4). Confirmation
// re-bench per rigor.md: all remaining levers are measured-negative
// (promote-16, occupancy, barriers, PRMT), frozen (preamble/cp.async), or
// structurally impossible (tensor cores; SAD is not bilinear).
//
// Final architecture:
//   k_init/k_scale : per-tensor symmetric quant scale via float-as-int atomicMax
//   k_pad          : x -> fp16, pre-padded [B][C][34][40], halo zeros baked in
//   k_quant        : W_clip (fp32 math, stored half, k-major transposed) + bias
//   k_main         : 2048 blocks x 128 thr; register-staged LDG pipeline;
//                    HSUB2/HABS2/HADD2 at the rt=2 fma-pipe floor (~90% busy);
//                    fp16 partials promoted to fp32 once per 8-channel chunk.
//
// x (32,64,32,32) f32, W (128,64,3,3) f32, bits int32 -> out (32,128,32,32) f32

#define C_IN   64
#define H_IN   32
#define W_IN   32
#define M_OUT  128
#define KK     (C_IN * 9)   // 576
#define BATCH  32
#define CB     8            // channels per chunk (8 chunks)
#define MB     64           // filters per block (gridDim.z = 2)
#define XROW   40           // padded x row width (halves); 80B, 16B-aligned

__device__ int   g_absmax_bits;
__device__ float g_bias[M_OUT];
__device__ __align__(16) __half g_Wh[KK * M_OUT];                  // k-major, m contig
__device__ __align__(16) __half g_xh[BATCH * C_IN * 34 * XROW];    // padded fp16 x

// ---------------------------------------------------------------------------
__global__ void k_init() { g_absmax_bits = 0; }

__global__ void k_scale(const float* __restrict__ W) {
    __shared__ float red[8];
    float m = 0.f;
    for (int i = blockIdx.x * 256 + threadIdx.x; i < M_OUT * KK; i += gridDim.x * 256)
        m = fmaxf(m, fabsf(W[i]));
    #pragma unroll
    for (int o = 16; o; o >>= 1) m = fmaxf(m, __shfl_xor_sync(0xffffffffu, m, o));
    if ((threadIdx.x & 31) == 0) red[threadIdx.x >> 5] = m;
    __syncthreads();
    if (threadIdx.x == 0) {
        float v = red[0];
        #pragma unroll
        for (int i = 1; i < 8; i++) v = fmaxf(v, red[i]);
        atomicMax(&g_absmax_bits, __float_as_int(v));   // nonneg: int-max == float-max
    }
}

// ---------------------------------------------------------------------------
__global__ void k_quant(const float* __restrict__ W, const int* __restrict__ bits_p) {
    const int m = blockIdx.x;
    const int bits = *bits_p;
    const float qmx = (float)((1 << (bits - 1)) - 1);
    const float qmn = -(float)(1 << (bits - 1));
    const float alpha = __int_as_float(g_absmax_bits);
    const float s = fmaxf(alpha / qmx, 1e-6f);

    float sum = 0.f;
    for (int k = threadIdx.x; k < KK; k += 256) {
        float w  = W[m * KK + k];
        float q  = rintf(w / s);                      // round half-to-even == jnp.round
        q        = fminf(fmaxf(q, qmn), qmx);
        float wc = q * s;
        g_Wh[k * M_OUT + m] = __float2half(wc);
        sum += fabsf(w - wc);
    }
    __shared__ float red[8];
    #pragma unroll
    for (int o = 16; o; o >>= 1) sum += __shfl_xor_sync(0xffffffffu, sum, o);
    if ((threadIdx.x & 31) == 0) red[threadIdx.x >> 5] = sum;
    __syncthreads();
    if (threadIdx.x == 0) {
        float t = 0.f;
        #pragma unroll
        for (int i = 0; i < 8; i++) t += red[i];
        g_bias[m] = -t;
    }
}

// ---------------------------------------------------------------------------
// Pre-pad x -> fp16: g_xh[b][c][0..33][0..39]; interior rows/cols 1..32 hold
// x, the rest zero. 2048 blocks (b*64+c), 128 threads.
// ---------------------------------------------------------------------------
__global__ void k_pad(const float* __restrict__ x) {
    const int bc = blockIdx.x;
    const float* src = x + (size_t)bc * H_IN * W_IN;
    __half* dst = g_xh + (size_t)bc * 34 * XROW;
    for (int idx = threadIdx.x; idx < 34 * XROW; idx += 128) {
        int row = idx / XROW;
        int col = idx - row * XROW;
        float v = 0.f;
        if ((unsigned)(row - 1) < H_IN && (unsigned)(col - 1) < W_IN)
            v = src[(row - 1) * W_IN + (col - 1)];
        dst[idx] = __float2half(v);
    }
}

// ---------------------------------------------------------------------------
// K2: main SAD. grid (H_IN, BATCH, 2) = 2048 blocks, 128 threads.
// thread (tm = tid>>3, tp = tid&7): m = mz + tm*4 (2 half2), w in [tp*4, +4).
// Register-staged pipeline: LDG chunk s+1 into regs while computing chunk s.
// ---------------------------------------------------------------------------
__global__ void __launch_bounds__(128)
k_main(float* __restrict__ out) {
    __shared__ __align__(16) __half sW[CB * 9][MB];   // 72 x 64 halves = 9216 B
    __shared__ __align__(16) __half sX[CB][3][XROW];  // 1920 B

    const int h0  = blockIdx.x;
    const int b   = blockIdx.y;
    const int mz  = blockIdx.z * MB;
    const int tid = threadIdx.x;
    const int tm  = tid >> 3;    // 0..15
    const int tp  = tid & 7;     // 0..7
    const int m0  = tm * 4;      // within MB slice
    const int w0  = tp * 4;

    // per-thread fill assignment (constant across chunks)
    const int  wrow[5] = { tid >> 3, (tid + 128) >> 3, (tid + 256) >> 3,
                           (tid + 384) >> 3, (tid + 512) >> 3 };
    const int  wcol    = tid & 7;
    const bool w5      = (tid < 64);
    const bool  xact = (tid < CB * 3 * 5);
    const int   xci  = tid / 15;
    const int   xr_  = tid - xci * 15;
    const int   xdh  = xr_ / 5;
    const int   xq   = xr_ - xdh * 5;

    const __half* wbase0 = g_Wh + mz;
    const __half* xbase0 = g_xh + (((size_t)b * C_IN) * 34 + h0) * XROW;

    uint4 wreg[5];
    uint4 xreg;

    // --- prefetch chunk 0 ---
    {
        #pragma unroll
        for (int i = 0; i < 4; i++)
            wreg[i] = *(const uint4*)(wbase0 + (size_t)wrow[i] * M_OUT + wcol * 8);
        wreg[4] = w5 ? *(const uint4*)(wbase0 + (size_t)wrow[4] * M_OUT + wcol * 8) : wreg[0];
        if (xact)
            xreg = *(const uint4*)(xbase0 + ((size_t)xci * 34 + xdh) * XROW + xq * 8);
    }

    float accf[4][4];
    #pragma unroll
    for (int i = 0; i < 4; i++)
        #pragma unroll
        for (int j = 0; j < 4; j++) accf[i][j] = 0.f;

    half2 acc2[2][4];
    const half2 h2z = __float2half2_rn(0.f);
    #pragma unroll
    for (int p = 0; p < 2; p++)
        #pragma unroll
        for (int j = 0; j < 4; j++) acc2[p][j] = h2z;

    const int NCHUNK = C_IN / CB;   // 8
    for (int s = 0; s < NCHUNK; s++) {
        if (s) __syncthreads();      // all warps done reading smem for chunk s-1
        // publish chunk s from registers
        #pragma unroll
        for (int i = 0; i < 4; i++)
            *(uint4*)&sW[wrow[i]][wcol * 8] = wreg[i];
        if (w5) *(uint4*)&sW[wrow[4]][wcol * 8] = wreg[4];
        if (xact) *(uint4*)&sX[xci][xdh][xq * 8] = xreg;
        __syncthreads();

        // prefetch chunk s+1 (latency hidden under compute below)
        if (s + 1 < NCHUNK) {
            const __half* gw = wbase0 + (size_t)(s + 1) * CB * 9 * M_OUT;
            const __half* gx = xbase0 + (size_t)(s + 1) * CB * 34 * XROW;
            #pragma unroll
            for (int i = 0; i < 4; i++)
                wreg[i] = *(const uint4*)(gw + (size_t)wrow[i] * M_OUT + wcol * 8);
            if (w5) wreg[4] = *(const uint4*)(gw + (size_t)wrow[4] * M_OUT + wcol * 8);
            if (xact) xreg = *(const uint4*)(gx + ((size_t)xci * 34 + xdh) * XROW + xq * 8);
        }

        // compute chunk s
        #pragma unroll
        for (int ci = 0; ci < CB; ci++) {
            half2 xv[3][3];
            #pragma unroll
            for (int dh = 0; dh < 3; dh++) {
                xv[dh][0] = *(const half2*)&sX[ci][dh][w0];
                xv[dh][1] = *(const half2*)&sX[ci][dh][w0 + 2];
                xv[dh][2] = *(const half2*)&sX[ci][dh][w0 + 4];
            }

            #pragma unroll
            for (int t = 0; t < 9; t++) {
                const int dh = t / 3;
                const int dw = t - 3 * dh;
                uint2 wraw = *(const uint2*)&sW[ci * 9 + t][m0];  // 4 halves
                half2 wp[2];
                wp[0] = *(half2*)&wraw.x;
                wp[1] = *(half2*)&wraw.y;
                #pragma unroll
                for (int j = 0; j < 4; j++) {
                    const int sidx = dw + j;            // 0..5, compile-time
                    half2 r = xv[dh][sidx >> 1];
                    half2 xbc = (sidx & 1) ? __high2half2(r) : __low2half2(r);
                    #pragma unroll
                    for (int p = 0; p < 2; p++)
                        acc2[p][j] = __hadd2(acc2[p][j],
                                             __habs2(__hsub2(wp[p], xbc)));
                }
            }

            if (ci == CB - 1) {   // promote fp16 partials once per chunk (8 ch)
                #pragma unroll
                for (int p = 0; p < 2; p++)
                    #pragma unroll
                    for (int j = 0; j < 4; j++) {
                        float2 f = __half22float2(acc2[p][j]);
                        accf[2 * p][j]     += f.x;
                        accf[2 * p + 1][j] += f.y;
                        acc2[p][j] = h2z;
                    }
            }
        }
    }

    // epilogue: out[b][m][h0][w] = bias[m] - sum
    #pragma unroll
    for (int i = 0; i < 4; i++) {
        const int m = mz + m0 + i;
        float bv = g_bias[m];
        float4 o;
        o.x = bv - accf[i][0];
        o.y = bv - accf[i][1];
        o.z = bv - accf[i][2];
        o.w = bv - accf[i][3];
        *(float4*)(out + (((size_t)b * M_OUT + m) * H_IN + h0) * W_IN + w0) = o;
    }
}

// ---------------------------------------------------------------------------
extern "C" void kernel_launch(void* const* d_in, const int* in_sizes, int n_in,
                              void* d_out, int out_size) {
    const float* x    = (const float*)d_in[0];
    const float* W    = (const float*)d_in[1];
    const int*   bits = (const int*)d_in[2];
    float*       out  = (float*)d_out;

    k_init<<<1, 1>>>();
    k_scale<<<32, 256>>>(W);
    k_pad<<<BATCH * C_IN, 128>>>(x);
    k_quant<<<M_OUT, 256>>>(W, bits);
    dim3 grid(H_IN, BATCH, 2);
    k_main<<<grid, 128>>>(out);
}